// round 1
// baseline (speedup 1.0000x reference)
#include <cuda_runtime.h>

#define IN_CHAN 4096
#define BATCH   16
#define NTOT    (3 * IN_CHAN)        // 12288 virtual output rows (q,k,v stacked)
#define KSPLIT  4
#define KS_LEN  (IN_CHAN / KSPLIT)   // 1024
#define TN      64                   // n-tile per block
#define KC      32                   // k-chunk per smem stage

// Scratch (device globals: no allocation allowed in kernel_launch)
__device__ float g_part[KSPLIT * NTOT * BATCH];   // 12.6 MB split-K partials
__device__ float g_qkv[3 * BATCH * IN_CHAN];      // 768 KB q,k,v

// ---------------------------------------------------------------------------
// Kernel 1: QKV GEMM.  out[gn, b] = sum_k w[gn% S][k] * x[b][k]  (partial over
// a 1024-wide K slice).  128 threads, tile 64n x 16b, thread tile 4n x 2b,
// float4 along k.  w tile XOR-swizzled in smem for conflict-free LDS.128.
// ---------------------------------------------------------------------------
__global__ __launch_bounds__(128) void qkv_gemm_kernel(
    const float* __restrict__ x,
    const float* __restrict__ wq,
    const float* __restrict__ wk,
    const float* __restrict__ wv)
{
    __shared__ float4 ws4[TN * 8];      // [nn][col]  (col = kq ^ ((nn>>2)&7))
    __shared__ float4 xs4[BATCH * 8];   // [b][kq]

    const int tid = threadIdx.x;
    const int gn0 = blockIdx.x * TN;
    const int mat = gn0 >> 12;
    const int n0  = gn0 & (IN_CHAN - 1);
    const int kb  = blockIdx.y * KS_LEN;
    const float* w = (mat == 0) ? wq : (mat == 1) ? wk : wv;

    const int tx = tid & 15;            // n-quad index: rows 4*tx .. 4*tx+3
    const int ty = tid >> 4;            // 0..7 -> batch pair
    const int b0 = ty * 2;

    const int nl = tid >> 3;            // loader row base (0..15)
    const int kl = tid & 7;             // loader k-quad

    float acc[4][2];
#pragma unroll
    for (int r = 0; r < 4; ++r) { acc[r][0] = 0.f; acc[r][1] = 0.f; }

    for (int c = 0; c < KS_LEN / KC; ++c) {
        const int k0 = kb + c * KC;
        __syncthreads();
#pragma unroll
        for (int r = 0; r < 4; ++r) {
            int nn  = nl + r * 16;
            int col = kl ^ ((nn >> 2) & 7);
            ws4[nn * 8 + col] =
                *(const float4*)(w + (size_t)(n0 + nn) * IN_CHAN + k0 + kl * 4);
        }
        xs4[tid] = *(const float4*)(x + (size_t)nl * IN_CHAN + k0 + kl * 4);
        __syncthreads();

#pragma unroll
        for (int kq = 0; kq < 8; ++kq) {
            float4 x0 = xs4[b0 * 8 + kq];
            float4 x1 = xs4[(b0 + 1) * 8 + kq];
#pragma unroll
            for (int r = 0; r < 4; ++r) {
                int nn = tx * 4 + r;
                float4 wv4 = ws4[nn * 8 + (kq ^ (tx & 7))];
                acc[r][0] = fmaf(wv4.x, x0.x, acc[r][0]);
                acc[r][0] = fmaf(wv4.y, x0.y, acc[r][0]);
                acc[r][0] = fmaf(wv4.z, x0.z, acc[r][0]);
                acc[r][0] = fmaf(wv4.w, x0.w, acc[r][0]);
                acc[r][1] = fmaf(wv4.x, x1.x, acc[r][1]);
                acc[r][1] = fmaf(wv4.y, x1.y, acc[r][1]);
                acc[r][1] = fmaf(wv4.z, x1.z, acc[r][1]);
                acc[r][1] = fmaf(wv4.w, x1.w, acc[r][1]);
            }
        }
    }

    const int p = blockIdx.y;
#pragma unroll
    for (int r = 0; r < 4; ++r) {
        int gn = gn0 + tx * 4 + r;
        g_part[((size_t)p * NTOT + gn) * BATCH + b0]     = acc[r][0];
        g_part[((size_t)p * NTOT + gn) * BATCH + b0 + 1] = acc[r][1];
    }
}

// ---------------------------------------------------------------------------
// Kernel 2: reduce split-K partials + bias -> g_qkv[mat][b][n]
// ---------------------------------------------------------------------------
__global__ __launch_bounds__(256) void reduce_bias_kernel(
    const float* __restrict__ bq,
    const float* __restrict__ bk,
    const float* __restrict__ bv)
{
    int idx = blockIdx.x * 256 + threadIdx.x;   // [0, 3*16*4096)
    int n   = idx & (IN_CHAN - 1);
    int b   = (idx >> 12) & (BATCH - 1);
    int mat = idx >> 16;
    int gn  = mat * IN_CHAN + n;

    float s = 0.f;
#pragma unroll
    for (int pp = 0; pp < KSPLIT; ++pp)
        s += g_part[((size_t)pp * NTOT + gn) * BATCH + b];

    const float* bias = (mat == 0) ? bq : (mat == 1) ? bk : bv;
    g_qkv[idx] = s + bias[n];
}

// ---------------------------------------------------------------------------
// Kernel 3: rank-1 attention.  out[b,i] = sum_j v_j e^{q_i k_j} / sum_j e^{q_i k_j}
// k_b, v_b staged in smem (32KB); exp via MUFU.EX2 (a = q * log2(e) hoisted).
// Grid (64 query-chunks, 16 batches), 64 threads (1 query / thread).
// ---------------------------------------------------------------------------
__global__ __launch_bounds__(64) void attn_kernel(float* __restrict__ out)
{
    __shared__ float4 ks4[IN_CHAN / 4];
    __shared__ float4 vs4[IN_CHAN / 4];

    const int b   = blockIdx.y;
    const int tid = threadIdx.x;

    const float4* kp = (const float4*)(g_qkv + (size_t)BATCH * IN_CHAN + (size_t)b * IN_CHAN);
    const float4* vp = (const float4*)(g_qkv + (size_t)2 * BATCH * IN_CHAN + (size_t)b * IN_CHAN);
#pragma unroll
    for (int t = tid; t < IN_CHAN / 4; t += 64) {
        ks4[t] = kp[t];
        vs4[t] = vp[t];
    }
    __syncthreads();

    const int i = blockIdx.x * 64 + tid;
    const float a = g_qkv[(size_t)b * IN_CHAN + i] * 1.4426950408889634f;

    float num0 = 0.f, num1 = 0.f, den0 = 0.f, den1 = 0.f;
#pragma unroll 2
    for (int j = 0; j < IN_CHAN / 4; ++j) {
        float4 kk = ks4[j];
        float4 vv = vs4[j];
        float e0, e1, e2, e3;
        asm("ex2.approx.ftz.f32 %0, %1;" : "=f"(e0) : "f"(a * kk.x));
        asm("ex2.approx.ftz.f32 %0, %1;" : "=f"(e1) : "f"(a * kk.y));
        asm("ex2.approx.ftz.f32 %0, %1;" : "=f"(e2) : "f"(a * kk.z));
        asm("ex2.approx.ftz.f32 %0, %1;" : "=f"(e3) : "f"(a * kk.w));
        num0 = fmaf(e0, vv.x, num0);
        den0 += e0;
        num1 = fmaf(e1, vv.y, num1);
        den1 += e1;
        num0 = fmaf(e2, vv.z, num0);
        den0 += e2;
        num1 = fmaf(e3, vv.w, num1);
        den1 += e3;
    }
    out[(size_t)b * IN_CHAN + i] = (num0 + num1) / (den0 + den1);
}

// ---------------------------------------------------------------------------
extern "C" void kernel_launch(void* const* d_in, const int* in_sizes, int n_in,
                              void* d_out, int out_size)
{
    (void)in_sizes; (void)n_in; (void)out_size;
    const float* x  = (const float*)d_in[0];
    const float* wq = (const float*)d_in[1];
    const float* bq = (const float*)d_in[2];
    const float* wk = (const float*)d_in[3];
    const float* bk = (const float*)d_in[4];
    const float* wv = (const float*)d_in[5];
    const float* bv = (const float*)d_in[6];
    float* out = (float*)d_out;

    qkv_gemm_kernel<<<dim3(NTOT / TN, KSPLIT), 128>>>(x, wq, wk, wv);
    reduce_bias_kernel<<<(3 * BATCH * IN_CHAN) / 256, 256>>>(bq, bk, bv);
    attn_kernel<<<dim3(IN_CHAN / 64, BATCH), 64>>>(out);
}

// round 2
// speedup vs baseline: 1.0735x; 1.0735x over previous
#include <cuda_runtime.h>
#include <cstdint>

#define IN_CHAN 4096
#define BATCH   16
#define NTOT    (3 * IN_CHAN)        // 12288 stacked output rows (q,k,v)
#define KSPLIT  8
#define KS_LEN  (IN_CHAN / KSPLIT)   // 512 k per block
#define TN      128                  // W rows per block
#define KC      32                   // k per W stage
#define NSTAGES (KS_LEN / KC)        // 16

// Scratch (device globals; no allocation allowed in kernel_launch)
__device__ float g_part[KSPLIT * NTOT * BATCH];   // split-K partials
__device__ float g_qkv[3 * BATCH * IN_CHAN];      // q,k,v

__device__ __forceinline__ void cp_async16(void* smem_ptr, const void* gptr) {
    uint32_t sa = (uint32_t)__cvta_generic_to_shared(smem_ptr);
    asm volatile("cp.async.cg.shared.global [%0], [%1], 16;\n" :: "r"(sa), "l"(gptr));
}
__device__ __forceinline__ void cp_commit() {
    asm volatile("cp.async.commit_group;\n");
}

// ---------------------------------------------------------------------------
// Kernel 1: QKV GEMM, split-K partials.
// Block: 256 threads. Tile: 128 W-rows x 16 batches x 512 k.
// Thread tile: 4 rows x 2 batches. x slice staged once (32KB smem);
// W double-buffered KC=32 stages via cp.async.
// ---------------------------------------------------------------------------
__global__ __launch_bounds__(256) void qkv_gemm_kernel(
    const float* __restrict__ x,
    const float* __restrict__ wq,
    const float* __restrict__ wk,
    const float* __restrict__ wv)
{
    __shared__ float4 xs4[BATCH * (KS_LEN / 4)];   // [b][kk4]  16*128 = 2048 f4 (32KB)
    __shared__ float4 ws4[2][TN * 8];              // [buf][row*8 + swizzled col] (2*16KB)

    const int tid = threadIdx.x;
    const int gn0 = blockIdx.x * TN;
    const int mat = gn0 >> 12;
    const int n0  = gn0 & (IN_CHAN - 1);
    const int kb  = blockIdx.y * KS_LEN;
    const float* w = (mat == 0) ? wq : (mat == 1) ? wk : wv;

    // loader mapping: 4 W rows per thread, contiguous 128B per 8 lanes
    const int lr = tid >> 3;            // base row (0..31), rows lr + 32*i
    const int lq = tid & 7;             // k-quad within stage

    // compute mapping: rg = row-group (4 rows), bg = batch pair
    const int rg = tid & 31;
    const int bg = tid >> 5;            // 0..7

    // ---- prologue: issue x slice + W stage 0, then W stage 1 ----
#pragma unroll
    for (int i = 0; i < 8; ++i) {
        int idx = tid + i * 256;        // [0, 2048)
        int b   = idx >> 7;
        int kk4 = idx & 127;
        cp_async16(&xs4[idx], x + (size_t)b * IN_CHAN + kb + kk4 * 4);
    }
#pragma unroll
    for (int i = 0; i < 4; ++i) {
        int r = lr + i * 32;
        cp_async16(&ws4[0][r * 8 + (lq ^ ((r >> 2) & 7))],
                   w + (size_t)(n0 + r) * IN_CHAN + kb + lq * 4);
    }
    cp_commit();   // group: x + W0
#pragma unroll
    for (int i = 0; i < 4; ++i) {
        int r = lr + i * 32;
        cp_async16(&ws4[1][r * 8 + (lq ^ ((r >> 2) & 7))],
                   w + (size_t)(n0 + r) * IN_CHAN + kb + KC + lq * 4);
    }
    cp_commit();   // group: W1

    float acc[4][2];
#pragma unroll
    for (int rr = 0; rr < 4; ++rr) { acc[rr][0] = 0.f; acc[rr][1] = 0.f; }

    for (int s = 0; s < NSTAGES; ++s) {
        if (s + 1 < NSTAGES) asm volatile("cp.async.wait_group 1;\n");
        else                 asm volatile("cp.async.wait_group 0;\n");
        __syncthreads();

        const float4* wb = ws4[s & 1];
        const int kk4base = s * 8;
#pragma unroll
        for (int kq = 0; kq < 8; ++kq) {
            float4 x0 = xs4[(bg * 2) * 128 + kk4base + kq];
            float4 x1 = xs4[(bg * 2 + 1) * 128 + kk4base + kq];
            int col = kq ^ (rg & 7);
#pragma unroll
            for (int rr = 0; rr < 4; ++rr) {
                float4 w4 = wb[(rg * 4 + rr) * 8 + col];
                acc[rr][0] = fmaf(w4.x, x0.x, acc[rr][0]);
                acc[rr][0] = fmaf(w4.y, x0.y, acc[rr][0]);
                acc[rr][0] = fmaf(w4.z, x0.z, acc[rr][0]);
                acc[rr][0] = fmaf(w4.w, x0.w, acc[rr][0]);
                acc[rr][1] = fmaf(w4.x, x1.x, acc[rr][1]);
                acc[rr][1] = fmaf(w4.y, x1.y, acc[rr][1]);
                acc[rr][1] = fmaf(w4.z, x1.z, acc[rr][1]);
                acc[rr][1] = fmaf(w4.w, x1.w, acc[rr][1]);
            }
        }
        __syncthreads();

        if (s + 2 < NSTAGES) {
            const int k0 = kb + (s + 2) * KC;
#pragma unroll
            for (int i = 0; i < 4; ++i) {
                int r = lr + i * 32;
                cp_async16(&ws4[s & 1][r * 8 + (lq ^ ((r >> 2) & 7))],
                           w + (size_t)(n0 + r) * IN_CHAN + k0 + lq * 4);
            }
            cp_commit();
        }
    }

    const int p = blockIdx.y;
    const int b0 = bg * 2;
#pragma unroll
    for (int rr = 0; rr < 4; ++rr) {
        int gn = gn0 + rg * 4 + rr;
        g_part[((size_t)p * NTOT + gn) * BATCH + b0]     = acc[rr][0];
        g_part[((size_t)p * NTOT + gn) * BATCH + b0 + 1] = acc[rr][1];
    }
}

// ---------------------------------------------------------------------------
// Kernel 2: reduce split-K partials + bias -> g_qkv[mat][b][n]
// ---------------------------------------------------------------------------
__global__ __launch_bounds__(256) void reduce_bias_kernel(
    const float* __restrict__ bq,
    const float* __restrict__ bk,
    const float* __restrict__ bv)
{
    int idx = blockIdx.x * 256 + threadIdx.x;   // [0, 3*16*4096)
    int n   = idx & (IN_CHAN - 1);
    int b   = (idx >> 12) & (BATCH - 1);
    int mat = idx >> 16;
    int gn  = mat * IN_CHAN + n;

    float s = 0.f;
#pragma unroll
    for (int pp = 0; pp < KSPLIT; ++pp)
        s += g_part[((size_t)pp * NTOT + gn) * BATCH + b];

    const float* bias = (mat == 0) ? bq : (mat == 1) ? bk : bv;
    g_qkv[idx] = s + bias[n];
}

// ---------------------------------------------------------------------------
// Kernel 3: rank-1 attention.  out[b,i] = sum_j v_j e^{q_i k_j} / sum_j e^{q_i k_j}
// k_b, v_b staged in smem (32KB); exp via MUFU.EX2 (a = q * log2(e) hoisted).
// MUFU-bound by design (~8 cyc/exp per SMSP).
// ---------------------------------------------------------------------------
__global__ __launch_bounds__(64) void attn_kernel(float* __restrict__ out)
{
    __shared__ float4 ks4[IN_CHAN / 4];
    __shared__ float4 vs4[IN_CHAN / 4];

    const int b   = blockIdx.y;
    const int tid = threadIdx.x;

    const float4* kp = (const float4*)(g_qkv + (size_t)BATCH * IN_CHAN + (size_t)b * IN_CHAN);
    const float4* vp = (const float4*)(g_qkv + (size_t)2 * BATCH * IN_CHAN + (size_t)b * IN_CHAN);
#pragma unroll
    for (int t = tid; t < IN_CHAN / 4; t += 64) {
        ks4[t] = kp[t];
        vs4[t] = vp[t];
    }
    __syncthreads();

    const int i = blockIdx.x * 64 + tid;
    const float a = g_qkv[(size_t)b * IN_CHAN + i] * 1.4426950408889634f;

    float num0 = 0.f, num1 = 0.f, den0 = 0.f, den1 = 0.f;
#pragma unroll 2
    for (int j = 0; j < IN_CHAN / 4; ++j) {
        float4 kk = ks4[j];
        float4 vv = vs4[j];
        float e0, e1, e2, e3;
        asm("ex2.approx.ftz.f32 %0, %1;" : "=f"(e0) : "f"(a * kk.x));
        asm("ex2.approx.ftz.f32 %0, %1;" : "=f"(e1) : "f"(a * kk.y));
        asm("ex2.approx.ftz.f32 %0, %1;" : "=f"(e2) : "f"(a * kk.z));
        asm("ex2.approx.ftz.f32 %0, %1;" : "=f"(e3) : "f"(a * kk.w));
        num0 = fmaf(e0, vv.x, num0);
        den0 += e0;
        num1 = fmaf(e1, vv.y, num1);
        den1 += e1;
        num0 = fmaf(e2, vv.z, num0);
        den0 += e2;
        num1 = fmaf(e3, vv.w, num1);
        den1 += e3;
    }
    out[(size_t)b * IN_CHAN + i] = (num0 + num1) / (den0 + den1);
}

// ---------------------------------------------------------------------------
extern "C" void kernel_launch(void* const* d_in, const int* in_sizes, int n_in,
                              void* d_out, int out_size)
{
    (void)in_sizes; (void)n_in; (void)out_size;
    const float* x  = (const float*)d_in[0];
    const float* wq = (const float*)d_in[1];
    const float* bq = (const float*)d_in[2];
    const float* wk = (const float*)d_in[3];
    const float* bk = (const float*)d_in[4];
    const float* wv = (const float*)d_in[5];
    const float* bv = (const float*)d_in[6];
    float* out = (float*)d_out;

    qkv_gemm_kernel<<<dim3(NTOT / TN, KSPLIT), 256>>>(x, wq, wk, wv);
    reduce_bias_kernel<<<(3 * BATCH * IN_CHAN) / 256, 256>>>(bq, bk, bv);
    attn_kernel<<<dim3(IN_CHAN / 64, BATCH), 64>>>(out);
}

// round 3
// speedup vs baseline: 1.2885x; 1.2002x over previous
#include <cuda_runtime.h>
#include <cstdint>

#define IN_CHAN 4096
#define BATCH   16
#define NTOT    (3 * IN_CHAN)          // 12288 stacked W rows (q,k,v)
#define KSPLIT  8
#define KS_LEN  (IN_CHAN / KSPLIT)     // 512 k per block
#define ROWS_PB 32                     // rows per block (8 warps x 4 rows)
#define NNODES  32
#define LOG2E   1.4426950408889634f
#define PI_F    3.14159265358979323846f

// Scratch (device globals; no allocation allowed anywhere)
__device__ float g_part[KSPLIT * NTOT * BATCH];     // split-K partials
__device__ float g_qkv[3 * BATCH * IN_CHAN];        // q,k,v
__device__ float g_range[BATCH * 2];                // per-batch (center, halfwidth)
__device__ float g_nodes[BATCH][4][2][NNODES];      // per j-chunk partial F,G at nodes
__device__ float g_cheb[BATCH][2 * NNODES];         // Chebyshev coeffs: F then G

__device__ __forceinline__ void cp_async16(void* smem_ptr, const void* gptr) {
    uint32_t sa = (uint32_t)__cvta_generic_to_shared(smem_ptr);
    asm volatile("cp.async.cg.shared.global [%0], [%1], 16;\n" :: "r"(sa), "l"(gptr));
}
__device__ __forceinline__ float ex2(float x) {
    float r;
    asm("ex2.approx.ftz.f32 %0, %1;" : "=f"(r) : "f"(x));
    return r;
}

// ---------------------------------------------------------------------------
// Kernel 1: QKV GEMM, split-K. W never touches smem: each lane streams its own
// row chunk via coalesced LDG.128 and reuses it across all 16 batches (x in
// smem, conflict-free broadcast LDS). Warp = 4 rows x 8 k-quads.
// Block: 256 thr, 32 rows, 512 k.  End: 8-lane shfl reduce, one store.
// ---------------------------------------------------------------------------
__global__ __launch_bounds__(256) void qkv_gemm_kernel(
    const float* __restrict__ x,
    const float* __restrict__ wq,
    const float* __restrict__ wk,
    const float* __restrict__ wv)
{
    __shared__ float4 xs4[BATCH * (KS_LEN / 4)];   // [b][kk4] 16*128 f4 = 32KB

    const int tid  = threadIdx.x;
    const int wid  = tid >> 5;
    const int lane = tid & 31;
    const int kq   = lane & 7;          // k-quad offset within 8-group
    const int rsub = lane >> 3;         // row within warp (0..3)

    const int gn0 = blockIdx.x * ROWS_PB;
    const int mat = gn0 >> 12;
    const int n0  = gn0 & (IN_CHAN - 1);
    const int kb  = blockIdx.y * KS_LEN;
    const float* w = (mat == 0) ? wq : (mat == 1) ? wk : wv;

    // stage x slice (16 batches x 512 k)
#pragma unroll
    for (int i = 0; i < 8; ++i) {
        int idx = tid + i * 256;        // [0,2048)
        int b   = idx >> 7;
        int kk4 = idx & 127;
        cp_async16(&xs4[idx], x + (size_t)b * IN_CHAN + kb + kk4 * 4);
    }
    asm volatile("cp.async.commit_group;\ncp.async.wait_group 0;\n");
    __syncthreads();

    const int row = n0 + wid * 4 + rsub;
    const float* wp = w + (size_t)row * IN_CHAN + kb + kq * 4;

    float acc[BATCH];
#pragma unroll
    for (int b = 0; b < BATCH; ++b) acc[b] = 0.f;

    float4 wv4 = *(const float4*)wp;
#pragma unroll 2
    for (int it = 0; it < KS_LEN / 32; ++it) {      // 16 iters, 32 k each
        float4 cur = wv4;
        if (it + 1 < KS_LEN / 32)
            wv4 = *(const float4*)(wp + (it + 1) * 32);
        const int xi = it * 8 + kq;
#pragma unroll
        for (int b = 0; b < BATCH; ++b) {
            float4 x4 = xs4[b * 128 + xi];
            acc[b] = fmaf(cur.x, x4.x, acc[b]);
            acc[b] = fmaf(cur.y, x4.y, acc[b]);
            acc[b] = fmaf(cur.z, x4.z, acc[b]);
            acc[b] = fmaf(cur.w, x4.w, acc[b]);
        }
    }

    // reduce across the 8 lanes (kq 0..7) that share this row
#pragma unroll
    for (int b = 0; b < BATCH; ++b) {
        acc[b] += __shfl_xor_sync(0xffffffffu, acc[b], 1);
        acc[b] += __shfl_xor_sync(0xffffffffu, acc[b], 2);
        acc[b] += __shfl_xor_sync(0xffffffffu, acc[b], 4);
    }
    if (kq == 0) {
        const int p  = blockIdx.y;
        const int gn = gn0 + wid * 4 + rsub;
        float* dst = g_part + ((size_t)p * NTOT + gn) * BATCH;
#pragma unroll
        for (int v = 0; v < 4; ++v) {
            float4 o = make_float4(acc[v * 4], acc[v * 4 + 1],
                                   acc[v * 4 + 2], acc[v * 4 + 3]);
            *(float4*)(dst + v * 4) = o;
        }
    }
}

// ---------------------------------------------------------------------------
// Kernel 2: reduce split-K partials + bias -> g_qkv[mat][b][n]
// ---------------------------------------------------------------------------
__global__ __launch_bounds__(256) void reduce_bias_kernel(
    const float* __restrict__ bq,
    const float* __restrict__ bk,
    const float* __restrict__ bv)
{
    int idx = blockIdx.x * 256 + threadIdx.x;
    int n   = idx & (IN_CHAN - 1);
    int b   = (idx >> 12) & (BATCH - 1);
    int mat = idx >> 16;
    int gn  = mat * IN_CHAN + n;

    float s = 0.f;
#pragma unroll
    for (int pp = 0; pp < KSPLIT; ++pp)
        s += g_part[((size_t)pp * NTOT + gn) * BATCH + b];

    const float* bias = (mat == 0) ? bq : (mat == 1) ? bk : bv;
    g_qkv[idx] = s + bias[n];
}

// ---------------------------------------------------------------------------
// Kernel 3: per-batch q range -> (center, halfwidth)
// ---------------------------------------------------------------------------
__global__ __launch_bounds__(256) void q_range_kernel()
{
    __shared__ float smn[8], smx[8];
    const int b   = blockIdx.x;
    const int tid = threadIdx.x;
    const float* q = g_qkv + (size_t)b * IN_CHAN;

    float mn = 3.4e38f, mx = -3.4e38f;
    for (int i = tid; i < IN_CHAN; i += 256) {
        float v = q[i];
        mn = fminf(mn, v);
        mx = fmaxf(mx, v);
    }
#pragma unroll
    for (int o = 16; o; o >>= 1) {
        mn = fminf(mn, __shfl_xor_sync(0xffffffffu, mn, o));
        mx = fmaxf(mx, __shfl_xor_sync(0xffffffffu, mx, o));
    }
    if ((tid & 31) == 0) { smn[tid >> 5] = mn; smx[tid >> 5] = mx; }
    __syncthreads();
    if (tid == 0) {
        for (int i = 1; i < 8; ++i) {
            mn = fminf(mn, smn[i]);
            mx = fmaxf(mx, smx[i]);
        }
        g_range[b * 2]     = 0.5f * (mn + mx);
        g_range[b * 2 + 1] = fmaxf(0.5f * (mx - mn), 1e-6f);
    }
}

// ---------------------------------------------------------------------------
// Kernel 4: evaluate F,G at 32 Chebyshev nodes, partial over a 1024-j chunk.
// grid (16 batches, 4 chunks) x 512 thr.  thread = (node, j-sublane of 16).
// ---------------------------------------------------------------------------
__global__ __launch_bounds__(512) void attn_nodes_kernel()
{
    __shared__ float ks[1024], vs[1024];
    const int b   = blockIdx.x;
    const int ch  = blockIdx.y;
    const int tid = threadIdx.x;

    const float* kp = g_qkv + (size_t)BATCH * IN_CHAN + (size_t)b * IN_CHAN + ch * 1024;
    const float* vp = g_qkv + (size_t)2 * BATCH * IN_CHAN + (size_t)b * IN_CHAN + ch * 1024;
    for (int i = tid; i < 1024; i += 512) {
        ks[i] = kp[i];
        vs[i] = vp[i];
    }
    __syncthreads();

    const float qc = g_range[b * 2];
    const float qh = g_range[b * 2 + 1];
    const int node = tid >> 4;          // 0..31
    const int sub  = tid & 15;

    const float xt = qc + qh * cosf(PI_F * (node + 0.5f) / NNODES);
    const float a  = xt * LOG2E;

    float aF = 0.f, aG = 0.f;
#pragma unroll 4
    for (int j = sub; j < 1024; j += 16) {
        float e = ex2(a * ks[j]);
        aG += e;
        aF = fmaf(e, vs[j], aF);
    }
#pragma unroll
    for (int o = 8; o; o >>= 1) {
        aF += __shfl_xor_sync(0xffffffffu, aF, o);
        aG += __shfl_xor_sync(0xffffffffu, aG, o);
    }
    if (sub == 0) {
        g_nodes[b][ch][0][node] = aF;
        g_nodes[b][ch][1][node] = aG;
    }
}

// ---------------------------------------------------------------------------
// Kernel 5: reduce chunk partials + DCT -> Chebyshev coefficients.
// grid 16 x 64 thr.  thread m computes c_m for F (tid<32) or G (tid>=32).
// ---------------------------------------------------------------------------
__global__ __launch_bounds__(64) void attn_fit_kernel()
{
    __shared__ float Fv[NNODES], Gv[NNODES], tab[128];
    const int b   = blockIdx.x;
    const int tid = threadIdx.x;

    if (tid < NNODES) {
        float f = 0.f, g = 0.f;
#pragma unroll
        for (int c = 0; c < 4; ++c) {
            f += g_nodes[b][c][0][tid];
            g += g_nodes[b][c][1][tid];
        }
        Fv[tid] = f;
        Gv[tid] = g;
    }
    for (int u = tid; u < 128; u += 64)
        tab[u] = cosf((PI_F / 64.0f) * (float)u);
    __syncthreads();

    const int m = tid & 31;
    const float* src = (tid < 32) ? Fv : Gv;
    float c = 0.f;
#pragma unroll
    for (int t = 0; t < NNODES; ++t)
        c = fmaf(src[t], tab[(m * (2 * t + 1)) & 127], c);
    g_cheb[b][tid] = c * (2.0f / NNODES);
}

// ---------------------------------------------------------------------------
// Kernel 6: evaluate out[b,i] = F(q_i)/G(q_i) via Clenshaw.
// grid (16, 16) x 256 thr.
// ---------------------------------------------------------------------------
__global__ __launch_bounds__(256) void attn_eval_kernel(float* __restrict__ out)
{
    __shared__ float cF[NNODES], cG[NNODES];
    const int b   = blockIdx.y;
    const int tid = threadIdx.x;

    if (tid < 32)      cF[tid] = g_cheb[b][tid];
    else if (tid < 64) cG[tid - 32] = g_cheb[b][tid];
    __syncthreads();

    const float qc = g_range[b * 2];
    const float qh = g_range[b * 2 + 1];
    const int i = blockIdx.x * 256 + tid;

    float q = g_qkv[(size_t)b * IN_CHAN + i];
    float y = (q - qc) / qh;
    y = fminf(1.f, fmaxf(-1.f, y));
    const float y2 = 2.f * y;

    float f1 = 0.f, f2 = 0.f, g1 = 0.f, g2 = 0.f;
#pragma unroll
    for (int m = NNODES - 1; m >= 1; --m) {
        float tf = fmaf(y2, f1, cF[m] - f2);
        f2 = f1; f1 = tf;
        float tg = fmaf(y2, g1, cG[m] - g2);
        g2 = g1; g1 = tg;
    }
    float F = fmaf(y, f1, 0.5f * cF[0]) - f2;
    float G = fmaf(y, g1, 0.5f * cG[0]) - g2;

    out[(size_t)b * IN_CHAN + i] = F / G;
}

// ---------------------------------------------------------------------------
extern "C" void kernel_launch(void* const* d_in, const int* in_sizes, int n_in,
                              void* d_out, int out_size)
{
    (void)in_sizes; (void)n_in; (void)out_size;
    const float* x  = (const float*)d_in[0];
    const float* wq = (const float*)d_in[1];
    const float* bq = (const float*)d_in[2];
    const float* wk = (const float*)d_in[3];
    const float* bk = (const float*)d_in[4];
    const float* wv = (const float*)d_in[5];
    const float* bv = (const float*)d_in[6];
    float* out = (float*)d_out;

    qkv_gemm_kernel<<<dim3(NTOT / ROWS_PB, KSPLIT), 256>>>(x, wq, wk, wv);
    reduce_bias_kernel<<<(3 * BATCH * IN_CHAN) / 256, 256>>>(bq, bk, bv);
    q_range_kernel<<<BATCH, 256>>>();
    attn_nodes_kernel<<<dim3(BATCH, 4), 512>>>();
    attn_fit_kernel<<<BATCH, 64>>>();
    attn_eval_kernel<<<dim3(IN_CHAN / 256, BATCH), 256>>>(out);
}